// round 14
// baseline (speedup 1.0000x reference)
#include <cuda_runtime.h>
#include <cuda_fp16.h>
#include <cstdint>

#define K_DIM 4096
#define N_DIM 4096
#define M_MAX 8192

#define BM 128
#define BN 128
#define BK 32              // halves per k-tile (64 bytes per row)
#define STAGES 4
#define KTILES (K_DIM / BK)   // 128 (divisible by STAGES)

#define A_BYTES (BM * BK * 2)            // 8192
#define B_BYTES (BN * BK * 2)            // 8192
#define STAGE_BYTES (A_BYTES + B_BYTES)  // 16384
#define SMEM_TOTAL (STAGES * STAGE_BYTES)  // 65536

__device__ float  g_W [(size_t)N_DIM * K_DIM];
__device__ __align__(16) __half g_Wh[(size_t)N_DIM * K_DIM];
__device__ __align__(16) __half g_Xh[(size_t)M_MAX * K_DIM];

// ---------------------------------------------------------------------------
// helpers
// ---------------------------------------------------------------------------
__device__ __forceinline__ uint32_t smem_u32(const void* p) {
    uint32_t a;
    asm("{ .reg .u64 t; cvta.to.shared.u64 t, %1; cvt.u32.u64 %0, t; }"
        : "=r"(a) : "l"(p));
    return a;
}

// swizzled byte offset inside one operand tile (64B logical rows).
__device__ __forceinline__ uint32_t swz(int row, int c) {
    int line = row >> 1;
    int slot = (((row & 1) << 2) | c) ^ (line & 7);
    return (uint32_t)(line * 128 + slot * 16);
}

#define CP16(dst, src) \
    asm volatile("cp.async.cg.shared.global [%0], [%1], 16;" \
                 :: "r"(dst), "l"(src) : "memory")
#define CP_COMMIT() asm volatile("cp.async.commit_group;" ::: "memory")
#define CP_WAIT(n)  asm volatile("cp.async.wait_group %0;" :: "n"(n) : "memory")

#define LDSM_X4(r0, r1, r2, r3, addr)                                       \
    asm volatile("ldmatrix.sync.aligned.m8n8.x4.shared.b16 {%0,%1,%2,%3}, [%4];" \
                 : "=r"(r0), "=r"(r1), "=r"(r2), "=r"(r3) : "r"(addr))

__device__ __forceinline__ void mma_fp16(float* c, const uint32_t* a,
                                         uint32_t b0, uint32_t b1) {
    asm volatile(
        "mma.sync.aligned.m16n8k16.row.col.f32.f16.f16.f32 "
        "{%0,%1,%2,%3}, {%4,%5,%6,%7}, {%8,%9}, {%0,%1,%2,%3};"
        : "+f"(c[0]), "+f"(c[1]), "+f"(c[2]), "+f"(c[3])
        : "r"(a[0]), "r"(a[1]), "r"(a[2]), "r"(a[3]), "r"(b0), "r"(b1));
}

// ---------------------------------------------------------------------------
// prep kernels
// ---------------------------------------------------------------------------
// fused: zero g_W (independent of X) + convert X to fp16.
// group g < ZQ: zero 8 floats of g_W; else convert 8 floats of x.
#define ZQ ((size_t)N_DIM * K_DIM / 8)
__global__ void zero_convx_kernel(const float* __restrict__ x) {
    size_t g = (size_t)blockIdx.x * blockDim.x + threadIdx.x;
    if (g < ZQ) {
        size_t off = g * 8;
        *reinterpret_cast<float4*>(g_W + off)     = make_float4(0.f, 0.f, 0.f, 0.f);
        *reinterpret_cast<float4*>(g_W + off + 4) = make_float4(0.f, 0.f, 0.f, 0.f);
    } else {
        size_t off = (g - ZQ) * 8;
        float4 v0 = *reinterpret_cast<const float4*>(x + off);
        float4 v1 = *reinterpret_cast<const float4*>(x + off + 4);
        __half2 h[4];
        h[0] = __floats2half2_rn(v0.x, v0.y);
        h[1] = __floats2half2_rn(v0.z, v0.w);
        h[2] = __floats2half2_rn(v1.x, v1.y);
        h[3] = __floats2half2_rn(v1.z, v1.w);
        *reinterpret_cast<uint4*>(g_Xh + off) = *reinterpret_cast<uint4*>(h);
    }
}

// scatter, 2 triplets per thread (vectorized index/value loads)
__global__ void scatter2_kernel(const float* __restrict__ values,
                                const int* __restrict__ col_idx,
                                const int* __restrict__ row_ids, int nnz) {
    int i = (blockIdx.x * blockDim.x + threadIdx.x) * 2;
    if (i + 1 < nnz) {
        float2 v = *reinterpret_cast<const float2*>(values + i);
        int2   c = *reinterpret_cast<const int2*>(col_idx + i);
        int2   r = *reinterpret_cast<const int2*>(row_ids + i);
        atomicAdd(&g_W[(size_t)r.x * K_DIM + c.x], v.x);
        atomicAdd(&g_W[(size_t)r.y * K_DIM + c.y], v.y);
    } else if (i < nnz) {
        atomicAdd(&g_W[(size_t)row_ids[i] * K_DIM + col_idx[i]], values[i]);
    }
}

__global__ void conv_w_kernel() {
    size_t i = ((size_t)blockIdx.x * blockDim.x + threadIdx.x) * 8;
    float4 v0 = *reinterpret_cast<const float4*>(g_W + i);
    float4 v1 = *reinterpret_cast<const float4*>(g_W + i + 4);
    __half2 h[4];
    h[0] = __floats2half2_rn(v0.x, v0.y);
    h[1] = __floats2half2_rn(v0.z, v0.w);
    h[2] = __floats2half2_rn(v1.x, v1.y);
    h[3] = __floats2half2_rn(v1.z, v1.w);
    *reinterpret_cast<uint4*>(g_Wh + i) = *reinterpret_cast<uint4*>(h);
}

// ---------------------------------------------------------------------------
// GEMM: O[M, N_DIM] = Xh[M, K] * Wh[N, K]^T  (fp16 in, fp32 accum/out)
// CTA 128x128, BK=32, 4-stage cp.async, 8 warps as 4(m) x 2(n): warp 32x64.
// R13 mainloop verbatim (tensor=70.2%).
// ---------------------------------------------------------------------------
__global__ __launch_bounds__(256, 2)
void gemm_fp16_kernel(float* __restrict__ O) {
    extern __shared__ char smem[];
    const uint32_t sb = smem_u32(smem);

    const int tid  = threadIdx.x;
    const int warp = tid >> 5;
    const int lane = tid & 31;
    const int wm   = warp >> 1;          // 0..3
    const int wn   = warp & 1;           // 0..1
    const int bm   = blockIdx.y * BM;
    const int bn   = blockIdx.x * BN;

    // ---- producer mapping: 512 16B chunks per operand, 2 per thread ----
    const int prow0 = tid >> 2;          // 0..63
    const int pc    = tid & 3;           // chunk 0..3
    const int prow1 = prow0 + 64;

    const __half* pa0 = g_Xh + (size_t)(bm + prow0) * K_DIM + pc * 8;
    const __half* pa1 = g_Xh + (size_t)(bm + prow1) * K_DIM + pc * 8;
    const __half* pb0 = g_Wh + (size_t)(bn + prow0) * K_DIM + pc * 8;
    const __half* pb1 = g_Wh + (size_t)(bn + prow1) * K_DIM + pc * 8;

    const uint32_t dA0 = swz(prow0, pc), dA1 = swz(prow1, pc);

    // ---- consumer (ldmatrix) offsets ----
    uint32_t aoff[2][2];
#pragma unroll
    for (int mi = 0; mi < 2; mi++)
#pragma unroll
        for (int ks = 0; ks < 2; ks++)
            aoff[mi][ks] = swz(wm * 32 + mi * 16 + (lane & 15),
                               ks * 2 + (lane >> 4));
    uint32_t boff[2][2][2];
#pragma unroll
    for (int u = 0; u < 2; u++)
#pragma unroll
        for (int ks = 0; ks < 2; ks++)
#pragma unroll
            for (int h = 0; h < 2; h++)
                boff[u][ks][h] = swz(wn * 64 + u * 32 + lane, ks * 2 + h);

    float acc[2][8][4];
#pragma unroll
    for (int i = 0; i < 2; i++)
#pragma unroll
        for (int j = 0; j < 8; j++)
#pragma unroll
            for (int v = 0; v < 4; v++) acc[i][j][v] = 0.f;

    // ---- prologue: fill stages 0..STAGES-2 (tiles 0..2) ----
#pragma unroll
    for (int s = 0; s < STAGES - 1; s++) {
        const uint32_t ab = sb + s * STAGE_BYTES;
        const uint32_t bb = ab + A_BYTES;
        CP16(ab + dA0, pa0);
        CP16(ab + dA1, pa1);
        CP16(bb + dA0, pb0);
        CP16(bb + dA1, pb1);
        CP_COMMIT();
        pa0 += BK; pa1 += BK; pb0 += BK; pb1 += BK;
    }

    // ---- main loop: tiles 0..KTILES-STAGES-1, unconditional prefetch ----
    for (int kk = 0; kk < KTILES - STAGES; kk += STAGES) {
#pragma unroll
        for (int s = 0; s < STAGES; s++) {
            CP_WAIT(STAGES - 2);
            __syncthreads();

            {
                const uint32_t ab = sb + ((s + STAGES - 1) % STAGES) * STAGE_BYTES;
                const uint32_t bb = ab + A_BYTES;
                CP16(ab + dA0, pa0);
                CP16(ab + dA1, pa1);
                CP16(bb + dA0, pb0);
                CP16(bb + dA1, pb1);
                pa0 += BK; pa1 += BK; pb0 += BK; pb1 += BK;
            }
            CP_COMMIT();

            const uint32_t ab = sb + s * STAGE_BYTES;
            const uint32_t bb = ab + A_BYTES;
#pragma unroll
            for (int ks = 0; ks < 2; ks++) {
                uint32_t af[2][4];
#pragma unroll
                for (int mi = 0; mi < 2; mi++)
                    LDSM_X4(af[mi][0], af[mi][1], af[mi][2], af[mi][3],
                            ab + aoff[mi][ks]);
                uint32_t bf[8][2];
#pragma unroll
                for (int u = 0; u < 2; u++)
#pragma unroll
                    for (int h = 0; h < 2; h++) {
                        uint32_t q0, q1, q2, q3;
                        LDSM_X4(q0, q1, q2, q3, bb + boff[u][ks][h]);
                        bf[u * 4 + 0][h] = q0;
                        bf[u * 4 + 1][h] = q1;
                        bf[u * 4 + 2][h] = q2;
                        bf[u * 4 + 3][h] = q3;
                    }
#pragma unroll
                for (int mi = 0; mi < 2; mi++)
#pragma unroll
                    for (int j = 0; j < 8; j++)
                        mma_fp16(acc[mi][j], af[mi], bf[j][0], bf[j][1]);
            }
        }
    }

    // ---- tail: last STAGES k-tiles; s==0 prefetches the final tile ----
#pragma unroll
    for (int s = 0; s < STAGES; s++) {
        CP_WAIT(STAGES - 2);
        __syncthreads();

        if (s == 0) {
            const uint32_t ab = sb + ((STAGES - 1) % STAGES) * STAGE_BYTES;
            const uint32_t bb = ab + A_BYTES;
            CP16(ab + dA0, pa0);
            CP16(ab + dA1, pa1);
            CP16(bb + dA0, pb0);
            CP16(bb + dA1, pb1);
        }
        CP_COMMIT();

        const uint32_t ab = sb + s * STAGE_BYTES;
        const uint32_t bb = ab + A_BYTES;
#pragma unroll
        for (int ks = 0; ks < 2; ks++) {
            uint32_t af[2][4];
#pragma unroll
            for (int mi = 0; mi < 2; mi++)
                LDSM_X4(af[mi][0], af[mi][1], af[mi][2], af[mi][3],
                        ab + aoff[mi][ks]);
            uint32_t bf[8][2];
#pragma unroll
            for (int u = 0; u < 2; u++)
#pragma unroll
                for (int h = 0; h < 2; h++) {
                    uint32_t q0, q1, q2, q3;
                    LDSM_X4(q0, q1, q2, q3, bb + boff[u][ks][h]);
                    bf[u * 4 + 0][h] = q0;
                    bf[u * 4 + 1][h] = q1;
                    bf[u * 4 + 2][h] = q2;
                    bf[u * 4 + 3][h] = q3;
                }
#pragma unroll
            for (int mi = 0; mi < 2; mi++)
#pragma unroll
                for (int j = 0; j < 8; j++)
                    mma_fp16(acc[mi][j], af[mi], bf[j][0], bf[j][1]);
        }
    }

    // ---- epilogue ----
    const int tr = lane >> 2;            // 0..7
    const int tc = (lane & 3) * 2;
#pragma unroll
    for (int mi = 0; mi < 2; mi++) {
        const int row = bm + wm * 32 + mi * 16 + tr;
        float* o0 = O + (size_t)row * N_DIM;
        float* o1 = O + (size_t)(row + 8) * N_DIM;
#pragma unroll
        for (int j = 0; j < 8; j++) {
            const int col = bn + wn * 64 + j * 8 + tc;
            *reinterpret_cast<float2*>(o0 + col) =
                make_float2(acc[mi][j][0], acc[mi][j][1]);
            *reinterpret_cast<float2*>(o1 + col) =
                make_float2(acc[mi][j][2], acc[mi][j][3]);
        }
    }
}

// ---------------------------------------------------------------------------
extern "C" void kernel_launch(void* const* d_in, const int* in_sizes, int n_in,
                              void* d_out, int out_size) {
    const float* x      = (const float*)d_in[0];
    const float* values = (const float*)d_in[1];
    const int*   cols   = (const int*)d_in[2];
    const int*   rows   = (const int*)d_in[3];
    float*       out    = (float*)d_out;

    const int nnz = in_sizes[1];
    const int M   = in_sizes[0] / K_DIM;   // 8192

    // 1) fused: zero W + convert X (independent tasks, one launch)
    {
        const size_t total = ZQ + ((size_t)M * K_DIM / 8);
        zero_convx_kernel<<<(int)((total + 255) / 256), 256>>>(x);
    }
    // 2) scatter (2 triplets/thread)
    scatter2_kernel<<<(nnz / 2 + 255) / 256, 256>>>(values, cols, rows, nnz);
    // 3) convert W
    conv_w_kernel<<<(int)(((size_t)N_DIM * K_DIM / 8) / 256), 256>>>();

    cudaFuncSetAttribute(gemm_fp16_kernel,
                         cudaFuncAttributeMaxDynamicSharedMemorySize, SMEM_TOTAL);
    dim3 grid(N_DIM / BN, M / BM);   // (32, 64)
    gemm_fp16_kernel<<<grid, 256, SMEM_TOTAL>>>(out);
}

// round 15
// speedup vs baseline: 1.0161x; 1.0161x over previous
#include <cuda_runtime.h>
#include <cuda_fp16.h>
#include <cstdint>

#define K_DIM 4096
#define N_DIM 4096
#define M_MAX 8192

#define BM 128
#define BN 128
#define BK 32              // halves per k-tile (64 bytes per row)
#define STAGES 4
#define KTILES (K_DIM / BK)   // 128 (divisible by STAGES)

#define A_BYTES (BM * BK * 2)            // 8192
#define B_BYTES (BN * BK * 2)            // 8192
#define STAGE_BYTES (A_BYTES + B_BYTES)  // 16384
#define SMEM_TOTAL (STAGES * STAGE_BYTES)  // 65536

// g_W is zero-initialized at module load; conv_both re-zeroes it after
// consuming, so it is zeroed at entry of EVERY kernel_launch call.
__device__ float  g_W [(size_t)N_DIM * K_DIM];
__device__ __align__(16) __half g_Wh[(size_t)N_DIM * K_DIM];
__device__ __align__(16) __half g_Xh[(size_t)M_MAX * K_DIM];

// ---------------------------------------------------------------------------
// helpers
// ---------------------------------------------------------------------------
__device__ __forceinline__ uint32_t smem_u32(const void* p) {
    uint32_t a;
    asm("{ .reg .u64 t; cvta.to.shared.u64 t, %1; cvt.u32.u64 %0, t; }"
        : "=r"(a) : "l"(p));
    return a;
}

// swizzled byte offset inside one operand tile (64B logical rows).
__device__ __forceinline__ uint32_t swz(int row, int c) {
    int line = row >> 1;
    int slot = (((row & 1) << 2) | c) ^ (line & 7);
    return (uint32_t)(line * 128 + slot * 16);
}

#define CP16(dst, src) \
    asm volatile("cp.async.cg.shared.global [%0], [%1], 16;" \
                 :: "r"(dst), "l"(src) : "memory")
#define CP_COMMIT() asm volatile("cp.async.commit_group;" ::: "memory")
#define CP_WAIT(n)  asm volatile("cp.async.wait_group %0;" :: "n"(n) : "memory")

#define LDSM_X4(r0, r1, r2, r3, addr)                                       \
    asm volatile("ldmatrix.sync.aligned.m8n8.x4.shared.b16 {%0,%1,%2,%3}, [%4];" \
                 : "=r"(r0), "=r"(r1), "=r"(r2), "=r"(r3) : "r"(addr))

__device__ __forceinline__ void mma_fp16(float* c, const uint32_t* a,
                                         uint32_t b0, uint32_t b1) {
    asm volatile(
        "mma.sync.aligned.m16n8k16.row.col.f32.f16.f16.f32 "
        "{%0,%1,%2,%3}, {%4,%5,%6,%7}, {%8,%9}, {%0,%1,%2,%3};"
        : "+f"(c[0]), "+f"(c[1]), "+f"(c[2]), "+f"(c[3])
        : "r"(a[0]), "r"(a[1]), "r"(a[2]), "r"(a[3]), "r"(b0), "r"(b1));
}

// ---------------------------------------------------------------------------
// prep kernels
// ---------------------------------------------------------------------------
__global__ void scatter_kernel(const float* __restrict__ values,
                               const int* __restrict__ col_idx,
                               const int* __restrict__ row_ids, int nnz) {
    int i = blockIdx.x * blockDim.x + threadIdx.x;
    if (i < nnz)
        atomicAdd(&g_W[(size_t)row_ids[i] * K_DIM + col_idx[i]], values[i]);
}

// fused fp32->fp16 conversion of W (first WQ groups; re-zeroes g_W for the
// next call) and X (rest).
#define WQ ((size_t)N_DIM * K_DIM / 8)
__global__ void conv_both_kernel(const float* __restrict__ x) {
    size_t g = (size_t)blockIdx.x * blockDim.x + threadIdx.x;
    if (g < WQ) {
        size_t off = g * 8;
        float4 v0 = *reinterpret_cast<const float4*>(g_W + off);
        float4 v1 = *reinterpret_cast<const float4*>(g_W + off + 4);
        __half2 h[4];
        h[0] = __floats2half2_rn(v0.x, v0.y);
        h[1] = __floats2half2_rn(v0.z, v0.w);
        h[2] = __floats2half2_rn(v1.x, v1.y);
        h[3] = __floats2half2_rn(v1.z, v1.w);
        *reinterpret_cast<uint4*>(g_Wh + off) = *reinterpret_cast<uint4*>(h);
        // restore the all-zero invariant for the next launch/replay
        *reinterpret_cast<float4*>(g_W + off)     = make_float4(0.f, 0.f, 0.f, 0.f);
        *reinterpret_cast<float4*>(g_W + off + 4) = make_float4(0.f, 0.f, 0.f, 0.f);
    } else {
        size_t off = (g - WQ) * 8;
        float4 v0 = *reinterpret_cast<const float4*>(x + off);
        float4 v1 = *reinterpret_cast<const float4*>(x + off + 4);
        __half2 h[4];
        h[0] = __floats2half2_rn(v0.x, v0.y);
        h[1] = __floats2half2_rn(v0.z, v0.w);
        h[2] = __floats2half2_rn(v1.x, v1.y);
        h[3] = __floats2half2_rn(v1.z, v1.w);
        *reinterpret_cast<uint4*>(g_Xh + off) = *reinterpret_cast<uint4*>(h);
    }
}

// ---------------------------------------------------------------------------
// GEMM: O[M, N_DIM] = Xh[M, K] * Wh[N, K]^T  (fp16 in, fp32 accum/out)
// CTA 128x128, BK=32, 4-stage cp.async, 8 warps as 4(m) x 2(n): warp 32x64.
// R13 mainloop verbatim (tensor=70.2%).
// ---------------------------------------------------------------------------
__global__ __launch_bounds__(256, 2)
void gemm_fp16_kernel(float* __restrict__ O) {
    extern __shared__ char smem[];
    const uint32_t sb = smem_u32(smem);

    const int tid  = threadIdx.x;
    const int warp = tid >> 5;
    const int lane = tid & 31;
    const int wm   = warp >> 1;          // 0..3
    const int wn   = warp & 1;           // 0..1
    const int bm   = blockIdx.y * BM;
    const int bn   = blockIdx.x * BN;

    // ---- producer mapping: 512 16B chunks per operand, 2 per thread ----
    const int prow0 = tid >> 2;          // 0..63
    const int pc    = tid & 3;           // chunk 0..3
    const int prow1 = prow0 + 64;

    const __half* pa0 = g_Xh + (size_t)(bm + prow0) * K_DIM + pc * 8;
    const __half* pa1 = g_Xh + (size_t)(bm + prow1) * K_DIM + pc * 8;
    const __half* pb0 = g_Wh + (size_t)(bn + prow0) * K_DIM + pc * 8;
    const __half* pb1 = g_Wh + (size_t)(bn + prow1) * K_DIM + pc * 8;

    const uint32_t dA0 = swz(prow0, pc), dA1 = swz(prow1, pc);

    // ---- consumer (ldmatrix) offsets ----
    uint32_t aoff[2][2];
#pragma unroll
    for (int mi = 0; mi < 2; mi++)
#pragma unroll
        for (int ks = 0; ks < 2; ks++)
            aoff[mi][ks] = swz(wm * 32 + mi * 16 + (lane & 15),
                               ks * 2 + (lane >> 4));
    uint32_t boff[2][2][2];
#pragma unroll
    for (int u = 0; u < 2; u++)
#pragma unroll
        for (int ks = 0; ks < 2; ks++)
#pragma unroll
            for (int h = 0; h < 2; h++)
                boff[u][ks][h] = swz(wn * 64 + u * 32 + lane, ks * 2 + h);

    float acc[2][8][4];
#pragma unroll
    for (int i = 0; i < 2; i++)
#pragma unroll
        for (int j = 0; j < 8; j++)
#pragma unroll
            for (int v = 0; v < 4; v++) acc[i][j][v] = 0.f;

    // ---- prologue: fill stages 0..STAGES-2 (tiles 0..2) ----
#pragma unroll
    for (int s = 0; s < STAGES - 1; s++) {
        const uint32_t ab = sb + s * STAGE_BYTES;
        const uint32_t bb = ab + A_BYTES;
        CP16(ab + dA0, pa0);
        CP16(ab + dA1, pa1);
        CP16(bb + dA0, pb0);
        CP16(bb + dA1, pb1);
        CP_COMMIT();
        pa0 += BK; pa1 += BK; pb0 += BK; pb1 += BK;
    }

    // ---- main loop: tiles 0..KTILES-STAGES-1, unconditional prefetch ----
    for (int kk = 0; kk < KTILES - STAGES; kk += STAGES) {
#pragma unroll
        for (int s = 0; s < STAGES; s++) {
            CP_WAIT(STAGES - 2);
            __syncthreads();

            {
                const uint32_t ab = sb + ((s + STAGES - 1) % STAGES) * STAGE_BYTES;
                const uint32_t bb = ab + A_BYTES;
                CP16(ab + dA0, pa0);
                CP16(ab + dA1, pa1);
                CP16(bb + dA0, pb0);
                CP16(bb + dA1, pb1);
                pa0 += BK; pa1 += BK; pb0 += BK; pb1 += BK;
            }
            CP_COMMIT();

            const uint32_t ab = sb + s * STAGE_BYTES;
            const uint32_t bb = ab + A_BYTES;
#pragma unroll
            for (int ks = 0; ks < 2; ks++) {
                uint32_t af[2][4];
#pragma unroll
                for (int mi = 0; mi < 2; mi++)
                    LDSM_X4(af[mi][0], af[mi][1], af[mi][2], af[mi][3],
                            ab + aoff[mi][ks]);
                uint32_t bf[8][2];
#pragma unroll
                for (int u = 0; u < 2; u++)
#pragma unroll
                    for (int h = 0; h < 2; h++) {
                        uint32_t q0, q1, q2, q3;
                        LDSM_X4(q0, q1, q2, q3, bb + boff[u][ks][h]);
                        bf[u * 4 + 0][h] = q0;
                        bf[u * 4 + 1][h] = q1;
                        bf[u * 4 + 2][h] = q2;
                        bf[u * 4 + 3][h] = q3;
                    }
#pragma unroll
                for (int mi = 0; mi < 2; mi++)
#pragma unroll
                    for (int j = 0; j < 8; j++)
                        mma_fp16(acc[mi][j], af[mi], bf[j][0], bf[j][1]);
            }
        }
    }

    // ---- tail: last STAGES k-tiles; s==0 prefetches the final tile ----
#pragma unroll
    for (int s = 0; s < STAGES; s++) {
        CP_WAIT(STAGES - 2);
        __syncthreads();

        if (s == 0) {
            const uint32_t ab = sb + ((STAGES - 1) % STAGES) * STAGE_BYTES;
            const uint32_t bb = ab + A_BYTES;
            CP16(ab + dA0, pa0);
            CP16(ab + dA1, pa1);
            CP16(bb + dA0, pb0);
            CP16(bb + dA1, pb1);
        }
        CP_COMMIT();

        const uint32_t ab = sb + s * STAGE_BYTES;
        const uint32_t bb = ab + A_BYTES;
#pragma unroll
        for (int ks = 0; ks < 2; ks++) {
            uint32_t af[2][4];
#pragma unroll
            for (int mi = 0; mi < 2; mi++)
                LDSM_X4(af[mi][0], af[mi][1], af[mi][2], af[mi][3],
                        ab + aoff[mi][ks]);
            uint32_t bf[8][2];
#pragma unroll
            for (int u = 0; u < 2; u++)
#pragma unroll
                for (int h = 0; h < 2; h++) {
                    uint32_t q0, q1, q2, q3;
                    LDSM_X4(q0, q1, q2, q3, bb + boff[u][ks][h]);
                    bf[u * 4 + 0][h] = q0;
                    bf[u * 4 + 1][h] = q1;
                    bf[u * 4 + 2][h] = q2;
                    bf[u * 4 + 3][h] = q3;
                }
#pragma unroll
            for (int mi = 0; mi < 2; mi++)
#pragma unroll
                for (int j = 0; j < 8; j++)
                    mma_fp16(acc[mi][j], af[mi], bf[j][0], bf[j][1]);
        }
    }

    // ---- epilogue ----
    const int tr = lane >> 2;            // 0..7
    const int tc = (lane & 3) * 2;
#pragma unroll
    for (int mi = 0; mi < 2; mi++) {
        const int row = bm + wm * 32 + mi * 16 + tr;
        float* o0 = O + (size_t)row * N_DIM;
        float* o1 = O + (size_t)(row + 8) * N_DIM;
#pragma unroll
        for (int j = 0; j < 8; j++) {
            const int col = bn + wn * 64 + j * 8 + tc;
            *reinterpret_cast<float2*>(o0 + col) =
                make_float2(acc[mi][j][0], acc[mi][j][1]);
            *reinterpret_cast<float2*>(o1 + col) =
                make_float2(acc[mi][j][2], acc[mi][j][3]);
        }
    }
}

// ---------------------------------------------------------------------------
extern "C" void kernel_launch(void* const* d_in, const int* in_sizes, int n_in,
                              void* d_out, int out_size) {
    const float* x      = (const float*)d_in[0];
    const float* values = (const float*)d_in[1];
    const int*   cols   = (const int*)d_in[2];
    const int*   rows   = (const int*)d_in[3];
    float*       out    = (float*)d_out;

    const int nnz = in_sizes[1];
    const int M   = in_sizes[0] / K_DIM;   // 8192

    // g_W is all-zero at entry (module-load init + self-restore in conv_both).
    // 1) scatter values into g_W
    scatter_kernel<<<(nnz + 255) / 256, 256>>>(values, cols, rows, nnz);
    // 2) fused convert: W -> g_Wh (re-zeroing g_W), X -> g_Xh
    {
        const size_t total = WQ + ((size_t)M * K_DIM / 8);
        conv_both_kernel<<<(int)((total + 255) / 256), 256>>>(x);
    }

    cudaFuncSetAttribute(gemm_fp16_kernel,
                         cudaFuncAttributeMaxDynamicSharedMemorySize, SMEM_TOTAL);
    dim3 grid(N_DIM / BN, M / BM);   // (32, 64)
    gemm_fp16_kernel<<<grid, 256, SMEM_TOTAL>>>(out);
}

// round 16
// speedup vs baseline: 1.0248x; 1.0086x over previous
#include <cuda_runtime.h>
#include <cuda_fp16.h>
#include <cstdint>

#define K_DIM 4096
#define N_DIM 4096
#define M_MAX 8192

#define BM 128
#define BN 128
#define BK 32              // halves per k-tile (64 bytes per row)
#define STAGES 4
#define KTILES (K_DIM / BK)   // 128 (divisible by STAGES)

#define A_BYTES (BM * BK * 2)            // 8192
#define B_BYTES (BN * BK * 2)            // 8192
#define STAGE_BYTES (A_BYTES + B_BYTES)  // 16384
#define SMEM_TOTAL (STAGES * STAGE_BYTES)  // 65536

__device__ float  g_W [(size_t)N_DIM * K_DIM];
__device__ __align__(16) __half g_Wh[(size_t)N_DIM * K_DIM];
__device__ __align__(16) __half g_Xh[(size_t)M_MAX * K_DIM];

// ---------------------------------------------------------------------------
// helpers
// ---------------------------------------------------------------------------
__device__ __forceinline__ uint32_t smem_u32(const void* p) {
    uint32_t a;
    asm("{ .reg .u64 t; cvta.to.shared.u64 t, %1; cvt.u32.u64 %0, t; }"
        : "=r"(a) : "l"(p));
    return a;
}

// swizzled byte offset inside one operand tile (64B logical rows).
__device__ __forceinline__ uint32_t swz(int row, int c) {
    int line = row >> 1;
    int slot = (((row & 1) << 2) | c) ^ (line & 7);
    return (uint32_t)(line * 128 + slot * 16);
}

#define CP16(dst, src) \
    asm volatile("cp.async.cg.shared.global [%0], [%1], 16;" \
                 :: "r"(dst), "l"(src) : "memory")
#define CP_COMMIT() asm volatile("cp.async.commit_group;" ::: "memory")
#define CP_WAIT(n)  asm volatile("cp.async.wait_group %0;" :: "n"(n) : "memory")

#define LDSM_X4(r0, r1, r2, r3, addr)                                       \
    asm volatile("ldmatrix.sync.aligned.m8n8.x4.shared.b16 {%0,%1,%2,%3}, [%4];" \
                 : "=r"(r0), "=r"(r1), "=r"(r2), "=r"(r3) : "r"(addr))

__device__ __forceinline__ void mma_fp16(float* c, const uint32_t* a,
                                         uint32_t b0, uint32_t b1) {
    asm volatile(
        "mma.sync.aligned.m16n8k16.row.col.f32.f16.f16.f32 "
        "{%0,%1,%2,%3}, {%4,%5,%6,%7}, {%8,%9}, {%0,%1,%2,%3};"
        : "+f"(c[0]), "+f"(c[1]), "+f"(c[2]), "+f"(c[3])
        : "r"(a[0]), "r"(a[1]), "r"(a[2]), "r"(a[3]), "r"(b0), "r"(b1));
}

// ---------------------------------------------------------------------------
// prep kernels (R13-proven chain)
// ---------------------------------------------------------------------------
__global__ void zero_w_kernel() {
    size_t i = ((size_t)blockIdx.x * blockDim.x + threadIdx.x) * 4;
    *reinterpret_cast<float4*>(g_W + i) = make_float4(0.f, 0.f, 0.f, 0.f);
}

__global__ void scatter_kernel(const float* __restrict__ values,
                               const int* __restrict__ col_idx,
                               const int* __restrict__ row_ids, int nnz) {
    int i = blockIdx.x * blockDim.x + threadIdx.x;
    if (i < nnz)
        atomicAdd(&g_W[(size_t)row_ids[i] * K_DIM + col_idx[i]], values[i]);
}

// fused fp32->fp16 conversion of W (first WQ groups) and X (rest)
#define WQ ((size_t)N_DIM * K_DIM / 8)
__global__ void conv_both_kernel(const float* __restrict__ x) {
    size_t g = (size_t)blockIdx.x * blockDim.x + threadIdx.x;
    const float* src;
    __half* dst;
    size_t off;
    if (g < WQ) { src = g_W; dst = g_Wh; off = g * 8; }
    else        { src = x;   dst = g_Xh; off = (g - WQ) * 8; }
    float4 v0 = *reinterpret_cast<const float4*>(src + off);
    float4 v1 = *reinterpret_cast<const float4*>(src + off + 4);
    __half2 h[4];
    h[0] = __floats2half2_rn(v0.x, v0.y);
    h[1] = __floats2half2_rn(v0.z, v0.w);
    h[2] = __floats2half2_rn(v1.x, v1.y);
    h[3] = __floats2half2_rn(v1.z, v1.w);
    *reinterpret_cast<uint4*>(dst + off) = *reinterpret_cast<uint4*>(h);
}

// ---------------------------------------------------------------------------
// GEMM: O[M, N_DIM] = Xh[M, K] * Wh[N, K]^T  (fp16 in, fp32 accum/out)
// CTA 128x128, BK=32, 4-stage cp.async, 8 warps as 4(m) x 2(n): warp 32x64.
// R13 skeleton; issue order per tile: ks0-LDSM -> prefetch -> ks0-MMA ->
// ks1-LDSM -> ks1-MMA (cp.async dispatch hides in LDSM latency shadow).
// ---------------------------------------------------------------------------
__global__ __launch_bounds__(256, 2)
void gemm_fp16_kernel(float* __restrict__ O) {
    extern __shared__ char smem[];
    const uint32_t sb = smem_u32(smem);

    const int tid  = threadIdx.x;
    const int warp = tid >> 5;
    const int lane = tid & 31;
    const int wm   = warp >> 1;          // 0..3
    const int wn   = warp & 1;           // 0..1
    const int bm   = blockIdx.y * BM;
    const int bn   = blockIdx.x * BN;

    // ---- producer mapping: 512 16B chunks per operand, 2 per thread ----
    const int prow0 = tid >> 2;          // 0..63
    const int pc    = tid & 3;           // chunk 0..3
    const int prow1 = prow0 + 64;

    const __half* pa0 = g_Xh + (size_t)(bm + prow0) * K_DIM + pc * 8;
    const __half* pa1 = g_Xh + (size_t)(bm + prow1) * K_DIM + pc * 8;
    const __half* pb0 = g_Wh + (size_t)(bn + prow0) * K_DIM + pc * 8;
    const __half* pb1 = g_Wh + (size_t)(bn + prow1) * K_DIM + pc * 8;

    const uint32_t dA0 = swz(prow0, pc), dA1 = swz(prow1, pc);

    // ---- consumer (ldmatrix) offsets ----
    uint32_t aoff[2][2];
#pragma unroll
    for (int mi = 0; mi < 2; mi++)
#pragma unroll
        for (int ks = 0; ks < 2; ks++)
            aoff[mi][ks] = swz(wm * 32 + mi * 16 + (lane & 15),
                               ks * 2 + (lane >> 4));
    uint32_t boff[2][2][2];
#pragma unroll
    for (int u = 0; u < 2; u++)
#pragma unroll
        for (int ks = 0; ks < 2; ks++)
#pragma unroll
            for (int h = 0; h < 2; h++)
                boff[u][ks][h] = swz(wn * 64 + u * 32 + lane, ks * 2 + h);

    float acc[2][8][4];
#pragma unroll
    for (int i = 0; i < 2; i++)
#pragma unroll
        for (int j = 0; j < 8; j++)
#pragma unroll
            for (int v = 0; v < 4; v++) acc[i][j][v] = 0.f;

    // ---- prologue: fill stages 0..STAGES-2 (tiles 0..2) ----
#pragma unroll
    for (int s = 0; s < STAGES - 1; s++) {
        const uint32_t ab = sb + s * STAGE_BYTES;
        const uint32_t bb = ab + A_BYTES;
        CP16(ab + dA0, pa0);
        CP16(ab + dA1, pa1);
        CP16(bb + dA0, pb0);
        CP16(bb + dA1, pb1);
        CP_COMMIT();
        pa0 += BK; pa1 += BK; pb0 += BK; pb1 += BK;
    }

    // ---- main loop: tiles 0..KTILES-STAGES-1, unconditional prefetch ----
    for (int kk = 0; kk < KTILES - STAGES; kk += STAGES) {
#pragma unroll
        for (int s = 0; s < STAGES; s++) {
            CP_WAIT(STAGES - 2);
            __syncthreads();

            const uint32_t ab = sb + s * STAGE_BYTES;
            const uint32_t bb = ab + A_BYTES;

            // ---- ks = 0 fragment loads first (critical path) ----
            uint32_t af0[2][4];
#pragma unroll
            for (int mi = 0; mi < 2; mi++)
                LDSM_X4(af0[mi][0], af0[mi][1], af0[mi][2], af0[mi][3],
                        ab + aoff[mi][0]);
            uint32_t bf0[8][2];
#pragma unroll
            for (int u = 0; u < 2; u++)
#pragma unroll
                for (int h = 0; h < 2; h++) {
                    uint32_t q0, q1, q2, q3;
                    LDSM_X4(q0, q1, q2, q3, bb + boff[u][0][h]);
                    bf0[u * 4 + 0][h] = q0;
                    bf0[u * 4 + 1][h] = q1;
                    bf0[u * 4 + 2][h] = q2;
                    bf0[u * 4 + 3][h] = q3;
                }

            // ---- prefetch issues in the LDSM latency shadow ----
            {
                const uint32_t pab = sb + ((s + STAGES - 1) % STAGES) * STAGE_BYTES;
                const uint32_t pbb = pab + A_BYTES;
                CP16(pab + dA0, pa0);
                CP16(pab + dA1, pa1);
                CP16(pbb + dA0, pb0);
                CP16(pbb + dA1, pb1);
                pa0 += BK; pa1 += BK; pb0 += BK; pb1 += BK;
            }
            CP_COMMIT();

            // ---- ks = 0 MMAs ----
#pragma unroll
            for (int mi = 0; mi < 2; mi++)
#pragma unroll
                for (int j = 0; j < 8; j++)
                    mma_fp16(acc[mi][j], af0[mi], bf0[j][0], bf0[j][1]);

            // ---- ks = 1 loads + MMAs ----
            uint32_t af1[2][4];
#pragma unroll
            for (int mi = 0; mi < 2; mi++)
                LDSM_X4(af1[mi][0], af1[mi][1], af1[mi][2], af1[mi][3],
                        ab + aoff[mi][1]);
            uint32_t bf1[8][2];
#pragma unroll
            for (int u = 0; u < 2; u++)
#pragma unroll
                for (int h = 0; h < 2; h++) {
                    uint32_t q0, q1, q2, q3;
                    LDSM_X4(q0, q1, q2, q3, bb + boff[u][1][h]);
                    bf1[u * 4 + 0][h] = q0;
                    bf1[u * 4 + 1][h] = q1;
                    bf1[u * 4 + 2][h] = q2;
                    bf1[u * 4 + 3][h] = q3;
                }
#pragma unroll
            for (int mi = 0; mi < 2; mi++)
#pragma unroll
                for (int j = 0; j < 8; j++)
                    mma_fp16(acc[mi][j], af1[mi], bf1[j][0], bf1[j][1]);
        }
    }

    // ---- tail: last STAGES k-tiles; s==0 prefetches the final tile ----
#pragma unroll
    for (int s = 0; s < STAGES; s++) {
        CP_WAIT(STAGES - 2);
        __syncthreads();

        if (s == 0) {
            const uint32_t ab = sb + ((STAGES - 1) % STAGES) * STAGE_BYTES;
            const uint32_t bb = ab + A_BYTES;
            CP16(ab + dA0, pa0);
            CP16(ab + dA1, pa1);
            CP16(bb + dA0, pb0);
            CP16(bb + dA1, pb1);
        }
        CP_COMMIT();

        const uint32_t ab = sb + s * STAGE_BYTES;
        const uint32_t bb = ab + A_BYTES;
#pragma unroll
        for (int ks = 0; ks < 2; ks++) {
            uint32_t af[2][4];
#pragma unroll
            for (int mi = 0; mi < 2; mi++)
                LDSM_X4(af[mi][0], af[mi][1], af[mi][2], af[mi][3],
                        ab + aoff[mi][ks]);
            uint32_t bf[8][2];
#pragma unroll
            for (int u = 0; u < 2; u++)
#pragma unroll
                for (int h = 0; h < 2; h++) {
                    uint32_t q0, q1, q2, q3;
                    LDSM_X4(q0, q1, q2, q3, bb + boff[u][ks][h]);
                    bf[u * 4 + 0][h] = q0;
                    bf[u * 4 + 1][h] = q1;
                    bf[u * 4 + 2][h] = q2;
                    bf[u * 4 + 3][h] = q3;
                }
#pragma unroll
            for (int mi = 0; mi < 2; mi++)
#pragma unroll
                for (int j = 0; j < 8; j++)
                    mma_fp16(acc[mi][j], af[mi], bf[j][0], bf[j][1]);
        }
    }

    // ---- epilogue ----
    const int tr = lane >> 2;            // 0..7
    const int tc = (lane & 3) * 2;
#pragma unroll
    for (int mi = 0; mi < 2; mi++) {
        const int row = bm + wm * 32 + mi * 16 + tr;
        float* o0 = O + (size_t)row * N_DIM;
        float* o1 = O + (size_t)(row + 8) * N_DIM;
#pragma unroll
        for (int j = 0; j < 8; j++) {
            const int col = bn + wn * 64 + j * 8 + tc;
            *reinterpret_cast<float2*>(o0 + col) =
                make_float2(acc[mi][j][0], acc[mi][j][1]);
            *reinterpret_cast<float2*>(o1 + col) =
                make_float2(acc[mi][j][2], acc[mi][j][3]);
        }
    }
}

// ---------------------------------------------------------------------------
extern "C" void kernel_launch(void* const* d_in, const int* in_sizes, int n_in,
                              void* d_out, int out_size) {
    const float* x      = (const float*)d_in[0];
    const float* values = (const float*)d_in[1];
    const int*   cols   = (const int*)d_in[2];
    const int*   rows   = (const int*)d_in[3];
    float*       out    = (float*)d_out;

    const int nnz = in_sizes[1];
    const int M   = in_sizes[0] / K_DIM;   // 8192

    zero_w_kernel<<<(int)(((size_t)N_DIM * K_DIM / 4) / 256), 256>>>();
    scatter_kernel<<<(nnz + 255) / 256, 256>>>(values, cols, rows, nnz);
    {
        const size_t total = WQ + ((size_t)M * K_DIM / 8);
        conv_both_kernel<<<(int)((total + 255) / 256), 256>>>(x);
    }

    cudaFuncSetAttribute(gemm_fp16_kernel,
                         cudaFuncAttributeMaxDynamicSharedMemorySize, SMEM_TOTAL);
    dim3 grid(N_DIM / BN, M / BM);   // (32, 64)
    gemm_fp16_kernel<<<grid, 256, SMEM_TOTAL>>>(out);
}